// round 15
// baseline (speedup 1.0000x reference)
#include <cuda_runtime.h>
#include <cuda_fp16.h>
#include <math.h>

// Problem dims (fixed by dataset)
#define MAXN 50000
#define MAXE 850000   // 800000 edges + 50000 self loops
#define IN_DIM 256
#define H1DIM 128     // 8 heads * 16
#define HEADS1 8
#define H2DIM 64
#define NEG_SLOPE 0.2f
#define SCAN_B 1024

// ---------------- scratch (static device globals; no allocation) -------------
__device__ float  g_h1[MAXN * H1DIM];     // fp32 (for scores1)
__device__ __half g_h1h[MAXN * H1DIM];    // fp16 mirror (for agg1 gather)
__device__ float  g_s1src[MAXN * HEADS1];
__device__ float  g_s1dst[MAXN * HEADS1];
__device__ int    g_deg[MAXN];
__device__ int    g_rowptr[MAXN + 1];
__device__ int    g_cursor[MAXN];
__device__ int    g_esrc[MAXE];
__device__ float  g_out1[MAXN * H1DIM];
__device__ float  g_h2[MAXN * H2DIM];     // fp32 (for scores2)
__device__ __half g_h2h[MAXN * H2DIM];    // fp16 mirror (for agg2 gather)
__device__ float  g_s2src[MAXN];
__device__ float  g_s2dst[MAXN];
__device__ int    g_is64;

// ---------------- helpers -----------------------------------------------------
__device__ __forceinline__ int edge_at(const void* ei, size_t idx) {
    if (g_is64) return (int)((const long long*)ei)[idx];
    return ((const int*)ei)[idx];
}

__device__ __forceinline__ float to_tf32(float x) {
    float r;
    asm("cvt.rna.tf32.f32 %0, %1;" : "=f"(r) : "f"(x));
    return r;
}

__device__ __forceinline__ float4 tf32x4(float4 v) {
    v.x = to_tf32(v.x); v.y = to_tf32(v.y);
    v.z = to_tf32(v.z); v.w = to_tf32(v.w);
    return v;
}

__device__ __forceinline__ float lrelu(float v) {
    return (v > 0.f) ? v : NEG_SLOPE * v;
}

__device__ __forceinline__ void mma_tf32(float* d, const unsigned* a,
                                         unsigned b0, unsigned b1) {
    asm volatile(
        "mma.sync.aligned.m16n8k8.row.col.f32.tf32.tf32.f32 "
        "{%0,%1,%2,%3}, {%4,%5,%6,%7}, {%8,%9}, {%0,%1,%2,%3};"
        : "+f"(d[0]), "+f"(d[1]), "+f"(d[2]), "+f"(d[3])
        : "r"(a[0]), "r"(a[1]), "r"(a[2]), "r"(a[3]), "r"(b0), "r"(b1));
}

// ---------------- init: deg=1 everywhere + edge-dtype detect ------------------
__global__ void init_kernel(const int* __restrict__ ei32, int Nn) {
    int i = blockIdx.x * blockDim.x + threadIdx.x;
    if (i < Nn) g_deg[i] = 1;   // self loop pre-counted
    if (i == 0) {
        int all_zero = 1;
        for (int k = 0; k < 64; k++)
            if (ei32[2 * k + 1] != 0) { all_zero = 0; break; }
        g_is64 = all_zero;
    }
}

// ---------------- pipelined tf32 GEMM body (double-buffered smem) -------------
// Block tile 128 x BN, KB=16; 256 threads.
// WHICH==0: A=arg(x), C=g_h1/g_h1h.  WHICH==1: A=g_out1, C=g_h2/g_h2h.
template <int BN, int WHICH>
__device__ __forceinline__ void gemm_body(const float* __restrict__ Aarg,
                                          const float* __restrict__ B,
                                          int M, int K, int bidx) {
    const float* __restrict__ A = (WHICH == 0) ? Aarg : (const float*)g_out1;
    float*  __restrict__ C  = (WHICH == 0) ? g_h1  : g_h2;
    __half* __restrict__ Ch = (WHICH == 0) ? g_h1h : g_h2h;

    constexpr int KB   = 16;
    constexpr int NW_N = BN / 64;
    constexpr int WM   = 128 / (8 / NW_N);
    constexpr int MAT  = WM / 16;
    constexpr int NAT  = 8;
    constexpr int BLD  = (KB * BN) / (4 * 256);   // B float4 loads per thread (2 or 1)

    __shared__ float As[2][128][20];              // [buf][m][k]
    __shared__ float Bs[2][KB][BN + 4];           // [buf][k][n]

    const int tid  = threadIdx.x;
    const int wid  = tid >> 5;
    const int lane = tid & 31;
    const int wm   = (wid / NW_N) * WM;
    const int wn   = (wid % NW_N) * 64;
    const int bm   = bidx * 128;
    const int lq   = lane & 3;
    const int lg   = lane >> 2;

    float acc[MAT][NAT][4];
#pragma unroll
    for (int i = 0; i < MAT; i++)
#pragma unroll
        for (int j = 0; j < NAT; j++)
#pragma unroll
            for (int c = 0; c < 4; c++) acc[i][j][c] = 0.0f;

    float4 ra[2], rb[BLD];

    // register staging: A tile 128x16 = 512 float4 (2/thread); B tile KBxBN
    auto load_tile = [&](int k0) {
#pragma unroll
        for (int i = 0; i < 2; i++) {
            int idx = tid + i * 256;
            int row = idx >> 2;
            int kc  = (idx & 3) * 4;
            int gm  = bm + row;
            int gmc = (gm < M) ? gm : (M - 1);
            float4 v = *(const float4*)(A + (size_t)gmc * K + k0 + kc);
            if (gm >= M) v = make_float4(0.f, 0.f, 0.f, 0.f);
            ra[i] = tf32x4(v);
        }
#pragma unroll
        for (int i = 0; i < BLD; i++) {
            int idx = tid + i * 256;
            int kk  = idx / (BN / 4);
            int nc  = (idx % (BN / 4)) * 4;
            rb[i] = tf32x4(*(const float4*)(B + (size_t)(k0 + kk) * BN + nc));
        }
    };
    auto store_tile = [&](int buf) {
#pragma unroll
        for (int i = 0; i < 2; i++) {
            int idx = tid + i * 256;
            int row = idx >> 2;
            int kc  = (idx & 3) * 4;
            *(float4*)&As[buf][row][kc] = ra[i];
        }
#pragma unroll
        for (int i = 0; i < BLD; i++) {
            int idx = tid + i * 256;
            int kk  = idx / (BN / 4);
            int nc  = (idx % (BN / 4)) * 4;
            *(float4*)&Bs[buf][kk][nc] = rb[i];
        }
    };
    auto compute = [&](int buf) {
#pragma unroll
        for (int ks = 0; ks < KB; ks += 8) {
            unsigned a[MAT][4];
#pragma unroll
            for (int i = 0; i < MAT; i++) {
                int m0 = wm + i * 16;
                a[i][0] = __float_as_uint(As[buf][m0 + lg][ks + lq]);
                a[i][1] = __float_as_uint(As[buf][m0 + lg + 8][ks + lq]);
                a[i][2] = __float_as_uint(As[buf][m0 + lg][ks + lq + 4]);
                a[i][3] = __float_as_uint(As[buf][m0 + lg + 8][ks + lq + 4]);
            }
#pragma unroll
            for (int j = 0; j < NAT; j++) {
                unsigned b0 = __float_as_uint(Bs[buf][ks + lq][wn + j * 8 + lg]);
                unsigned b1 = __float_as_uint(Bs[buf][ks + lq + 4][wn + j * 8 + lg]);
#pragma unroll
                for (int i = 0; i < MAT; i++) mma_tf32(acc[i][j], a[i], b0, b1);
            }
        }
    };

    // pipeline: prologue fills buf 0
    load_tile(0);
    store_tile(0);
    __syncthreads();
    int cur = 0;
    for (int k0 = KB; k0 < K; k0 += KB) {
        load_tile(k0);          // LDGs in flight...
        compute(cur);           // ...hidden behind 2*NAT*MAT MMAs
        store_tile(cur ^ 1);
        __syncthreads();
        cur ^= 1;
    }
    compute(cur);

    // epilogue
#pragma unroll
    for (int i = 0; i < MAT; i++) {
#pragma unroll
        for (int j = 0; j < NAT; j++) {
            int gm = bm + wm + i * 16 + lg;
            int n0 = wn + j * 8 + 2 * lq;
            if (gm < M) {
                *(float2*)(C + (size_t)gm * BN + n0) =
                    make_float2(acc[i][j][0], acc[i][j][1]);
                *(__half2*)(Ch + (size_t)gm * BN + n0) =
                    __floats2half2_rn(acc[i][j][0], acc[i][j][1]);
            }
            if (gm + 8 < M) {
                *(float2*)(C + (size_t)(gm + 8) * BN + n0) =
                    make_float2(acc[i][j][2], acc[i][j][3]);
                *(__half2*)(Ch + (size_t)(gm + 8) * BN + n0) =
                    __floats2half2_rn(acc[i][j][2], acc[i][j][3]);
            }
        }
    }
}

// ---------------- K1: gemm1 blocks || histo blocks ----------------------------
__global__ __launch_bounds__(256)
void k1_gemm1_histo(const float* __restrict__ x, const float* __restrict__ W1,
                    const void* __restrict__ ei, int M, int E, int nGemmBlocks) {
    if ((int)blockIdx.x < nGemmBlocks) {
        gemm_body<H1DIM, 0>(x, W1, M, IN_DIM, blockIdx.x);
    } else {
        int e = (blockIdx.x - nGemmBlocks) * 256 + threadIdx.x;
        if (e < E) atomicAdd(&g_deg[edge_at(ei, (size_t)E + e)], 1);
    }
}

// ---------------- single-kernel coalesced scan (shfl-based) -------------------
// Each block: (a) offset = reduce(deg[0 .. b*1024)) with coalesced loads,
// (b) shfl-scan its own 1024 elements, (c) write rowptr/cursor coalesced.
__global__ __launch_bounds__(SCAN_B)
void scan_kernel(int Nn) {
    __shared__ int wsum[32];
    __shared__ int wpre[32];
    __shared__ int boff;
    int tid = threadIdx.x, b = blockIdx.x;
    int lane = tid & 31, w = tid >> 5;

    // (a) block offset
    int tot = 0;
    for (int i = tid; i < b * SCAN_B; i += SCAN_B) tot += g_deg[i];
#pragma unroll
    for (int o = 16; o > 0; o >>= 1) tot += __shfl_xor_sync(0xFFFFFFFFu, tot, o);
    if (lane == 0) wsum[w] = tot;
    __syncthreads();
    if (w == 0) {
        int s = wsum[lane];
#pragma unroll
        for (int o = 16; o > 0; o >>= 1) s += __shfl_xor_sync(0xFFFFFFFFu, s, o);
        if (lane == 0) boff = s;
    }

    // (b) per-block scan
    int i = b * SCAN_B + tid;
    int v = (i < Nn) ? g_deg[i] : 0;
    int incl = v;
#pragma unroll
    for (int o = 1; o < 32; o <<= 1) {
        int u = __shfl_up_sync(0xFFFFFFFFu, incl, o);
        if (lane >= o) incl += u;
    }
    if (lane == 31) wsum[w] = incl;     // reuse wsum as warp totals
    __syncthreads();                     // covers boff write + warp totals
    if (w == 0) {
        int t = wsum[lane];
        int inc = t;
#pragma unroll
        for (int o = 1; o < 32; o <<= 1) {
            int u = __shfl_up_sync(0xFFFFFFFFu, inc, o);
            if (lane >= o) inc += u;
        }
        wpre[lane] = inc - t;            // exclusive warp prefix
    }
    __syncthreads();

    int excl = boff + wpre[w] + incl - v;
    if (i < Nn) {
        g_rowptr[i] = excl;
        g_cursor[i] = excl;
    }
    if (i == Nn - 1) g_rowptr[Nn] = excl + v;
}

// ---------------- K2: scores1 blocks || scatter blocks -------------------------
__global__ __launch_bounds__(256)
void k2_scores1_scatter(const float* __restrict__ a1s, const float* __restrict__ a1d,
                        const void* __restrict__ ei, int Nn, int E, int nScoreBlocks) {
    if ((int)blockIdx.x < nScoreBlocks) {
        int idx = blockIdx.x * 256 + threadIdx.x;
        if (idx >= Nn * HEADS1) return;
        int n = idx >> 3, h = idx & 7;
        const float4* hp = (const float4*)(g_h1 + (size_t)n * H1DIM + h * 16);
        const float4* as = (const float4*)(a1s + h * 16);
        const float4* ad = (const float4*)(a1d + h * 16);
        float ss = 0.f, sd = 0.f;
#pragma unroll
        for (int q = 0; q < 4; q++) {
            float4 v = hp[q], s4 = as[q], d4 = ad[q];
            ss += v.x * s4.x + v.y * s4.y + v.z * s4.z + v.w * s4.w;
            sd += v.x * d4.x + v.y * d4.y + v.z * d4.z + v.w * d4.w;
        }
        g_s1src[idx] = ss;
        g_s1dst[idx] = sd;
    } else {
        int idx = (blockIdx.x - nScoreBlocks) * 256 + threadIdx.x;
        if (idx >= E + Nn) return;
        int src, dst;
        if (idx < E) {
            src = edge_at(ei, (size_t)idx);
            dst = edge_at(ei, (size_t)E + idx);
        } else {
            src = dst = idx - E;  // self loop
        }
        int pos = atomicAdd(&g_cursor[dst], 1);
        g_esrc[pos] = src;
    }
}

// ---------------- layer-1 softmax+agg (fp16 gather, coalesced esrc) -----------
__global__ __launch_bounds__(256)
void agg1_kernel(const float* __restrict__ b1, int Nn) {
    int warp = (blockIdx.x * blockDim.x + threadIdx.x) >> 5;
    int lane = threadIdx.x & 31;
    if (warp >= Nn) return;
    int beg = g_rowptr[warp], end = g_rowptr[warp + 1];
    const int head = lane >> 2;
    const float sdst = g_s1dst[(size_t)warp * HEADS1 + head];

    float4 acc = make_float4(0.f, 0.f, 0.f, 0.f);
    float s = 0.f;
    int j = beg;
    for (; j + 7 < end; j += 8) {
        int eidx = g_esrc[j + (lane & 7)];
        int   idx[8];
        float w[8];
        uint2 u[8];
#pragma unroll
        for (int t = 0; t < 8; t++) idx[t] = __shfl_sync(0xFFFFFFFFu, eidx, t);
#pragma unroll
        for (int t = 0; t < 8; t++)
            u[t] = *(const uint2*)(g_h1h + (size_t)idx[t] * H1DIM + lane * 4);
#pragma unroll
        for (int t = 0; t < 8; t++)
            w[t] = __expf(lrelu(g_s1src[(size_t)idx[t] * HEADS1 + head] + sdst));
#pragma unroll
        for (int t = 0; t < 8; t++) {
            s += w[t];
            float2 p = __half22float2(*(__half2*)&u[t].x);
            float2 q = __half22float2(*(__half2*)&u[t].y);
            acc.x = fmaf(w[t], p.x, acc.x); acc.y = fmaf(w[t], p.y, acc.y);
            acc.z = fmaf(w[t], q.x, acc.z); acc.w = fmaf(w[t], q.y, acc.w);
        }
    }
    for (; j < end; ++j) {
        int i0 = g_esrc[j];
        float w0 = __expf(lrelu(g_s1src[(size_t)i0 * HEADS1 + head] + sdst));
        uint2 u0 = *(const uint2*)(g_h1h + (size_t)i0 * H1DIM + lane * 4);
        s += w0;
        float2 p = __half22float2(*(__half2*)&u0.x);
        float2 q = __half22float2(*(__half2*)&u0.y);
        acc.x = fmaf(w0, p.x, acc.x); acc.y = fmaf(w0, p.y, acc.y);
        acc.z = fmaf(w0, q.x, acc.z); acc.w = fmaf(w0, q.y, acc.w);
    }
    float inv = 1.0f / s;
    float4 bb = *(const float4*)(b1 + lane * 4);
    float4 o;
    o.x = acc.x * inv + bb.x;  o.y = acc.y * inv + bb.y;
    o.z = acc.z * inv + bb.z;  o.w = acc.w * inv + bb.w;
    o.x = (o.x > 0.f) ? o.x : (__expf(o.x) - 1.0f);
    o.y = (o.y > 0.f) ? o.y : (__expf(o.y) - 1.0f);
    o.z = (o.z > 0.f) ? o.z : (__expf(o.z) - 1.0f);
    o.w = (o.w > 0.f) ? o.w : (__expf(o.w) - 1.0f);
    *(float4*)(g_out1 + (size_t)warp * H1DIM + lane * 4) = o;
}

// ---------------- gemm2 (standalone) ------------------------------------------
__global__ __launch_bounds__(256)
void gemm2_kernel(const float* __restrict__ W2, int M) {
    gemm_body<H2DIM, 1>(nullptr, W2, M, H1DIM, blockIdx.x);
}

// ---------------- layer-2 scores (warp per node) -------------------------------
__global__ __launch_bounds__(256)
void scores2_kernel(const float* __restrict__ a2s, const float* __restrict__ a2d, int Nn) {
    int warp = (blockIdx.x * blockDim.x + threadIdx.x) >> 5;
    int lane = threadIdx.x & 31;
    if (warp >= Nn) return;
    const float2 v  = *(const float2*)(g_h2 + (size_t)warp * H2DIM + lane * 2);
    const float2 s2 = *(const float2*)(a2s + lane * 2);
    const float2 d2 = *(const float2*)(a2d + lane * 2);
    float ss = v.x * s2.x + v.y * s2.y;
    float sd = v.x * d2.x + v.y * d2.y;
#pragma unroll
    for (int o = 16; o > 0; o >>= 1) {
        ss += __shfl_xor_sync(0xFFFFFFFFu, ss, o);
        sd += __shfl_xor_sync(0xFFFFFFFFu, sd, o);
    }
    if (lane == 0) {
        g_s2src[warp] = ss;
        g_s2dst[warp] = sd;
    }
}

// ---------------- layer-2 softmax+agg (fp16 gather, coalesced esrc) -----------
__global__ __launch_bounds__(256)
void agg2_kernel(const float* __restrict__ b2, float* __restrict__ dout, int Nn) {
    int warp = (blockIdx.x * blockDim.x + threadIdx.x) >> 5;
    int lane = threadIdx.x & 31;
    if (warp >= Nn) return;
    int beg = g_rowptr[warp], end = g_rowptr[warp + 1];
    const float sdst = g_s2dst[warp];

    float a0 = 0.f, a1 = 0.f, s = 0.f;
    int j = beg;
    for (; j + 7 < end; j += 8) {
        int eidx = g_esrc[j + (lane & 7)];
        int     idx[8];
        float   w[8];
        __half2 u[8];
#pragma unroll
        for (int t = 0; t < 8; t++) idx[t] = __shfl_sync(0xFFFFFFFFu, eidx, t);
#pragma unroll
        for (int t = 0; t < 8; t++)
            u[t] = *(const __half2*)(g_h2h + (size_t)idx[t] * H2DIM + lane * 2);
#pragma unroll
        for (int t = 0; t < 8; t++)
            w[t] = __expf(lrelu(g_s2src[idx[t]] + sdst));
#pragma unroll
        for (int t = 0; t < 8; t++) {
            s += w[t];
            float2 f = __half22float2(u[t]);
            a0 = fmaf(w[t], f.x, a0); a1 = fmaf(w[t], f.y, a1);
        }
    }
    for (; j < end; ++j) {
        int i0 = g_esrc[j];
        float w0 = __expf(lrelu(g_s2src[i0] + sdst));
        __half2 u0 = *(const __half2*)(g_h2h + (size_t)i0 * H2DIM + lane * 2);
        s += w0;
        float2 f = __half22float2(u0);
        a0 = fmaf(w0, f.x, a0); a1 = fmaf(w0, f.y, a1);
    }
    float inv = 1.0f / s;
    float2 bb = *(const float2*)(b2 + lane * 2);
    float o0 = a0 * inv + bb.x;
    float o1 = a1 * inv + bb.y;

    float mx = fmaxf(o0, o1);
#pragma unroll
    for (int o = 16; o > 0; o >>= 1) mx = fmaxf(mx, __shfl_xor_sync(0xFFFFFFFFu, mx, o));
    float se = __expf(o0 - mx) + __expf(o1 - mx);
#pragma unroll
    for (int o = 16; o > 0; o >>= 1) se += __shfl_xor_sync(0xFFFFFFFFu, se, o);
    float lse = __logf(se);
    float2 r;  r.x = o0 - mx - lse;  r.y = o1 - mx - lse;
    *(float2*)(dout + (size_t)warp * H2DIM + lane * 2) = r;
}

// ---------------- launch (pure kernel launches, default stream) --------------
extern "C" void kernel_launch(void* const* d_in, const int* in_sizes, int n_in,
                              void* d_out, int out_size) {
    const float* x   = (const float*)d_in[0];
    const void*  ei  = d_in[1];
    const float* W1  = (const float*)d_in[2];
    const float* a1s = (const float*)d_in[3];
    const float* a1d = (const float*)d_in[4];
    const float* b1  = (const float*)d_in[5];
    const float* W2  = (const float*)d_in[6];
    const float* a2s = (const float*)d_in[7];
    const float* a2d = (const float*)d_in[8];
    const float* b2  = (const float*)d_in[9];
    float*       out = (float*)d_out;

    const int Nn   = in_sizes[0] / IN_DIM;  // 50000
    const int E    = in_sizes[1] / 2;       // 800000
    const int Etot = E + Nn;

    const int nG1 = (Nn + 127) / 128;             // gemm1 blocks
    const int nH  = (E + 255) / 256;              // histo blocks
    const int nS1 = (Nn * HEADS1 + 255) / 256;    // scores1 blocks
    const int nSc = (Etot + 255) / 256;           // scatter blocks
    const int nSB = (Nn + SCAN_B - 1) / SCAN_B;   // scan blocks (49)

    init_kernel<<<(Nn + 255) / 256, 256>>>((const int*)ei, Nn);
    k1_gemm1_histo<<<nG1 + nH, 256>>>(x, W1, ei, Nn, E, nG1);
    scan_kernel<<<nSB, SCAN_B>>>(Nn);
    k2_scores1_scatter<<<nS1 + nSc, 256>>>(a1s, a1d, ei, Nn, E, nS1);
    agg1_kernel<<<(Nn + 7) / 8, 256>>>(b1, Nn);

    gemm2_kernel<<<(Nn + 127) / 128, 256>>>(W2, Nn);
    scores2_kernel<<<(Nn + 7) / 8, 256>>>(a2s, a2d, Nn);
    agg2_kernel<<<(Nn + 7) / 8, 256>>>(b2, out, Nn);
}

// round 16
// speedup vs baseline: 1.0578x; 1.0578x over previous
#include <cuda_runtime.h>
#include <cuda_fp16.h>
#include <math.h>

// Problem dims (fixed by dataset)
#define MAXN 50000
#define MAXE 850000   // 800000 edges + 50000 self loops
#define IN_DIM 256
#define H1DIM 128     // 8 heads * 16
#define HEADS1 8
#define H2DIM 64
#define NEG_SLOPE 0.2f
#define SCAN_B 1024

// ---------------- scratch (static device globals; no allocation) -------------
__device__ float  g_h1[MAXN * H1DIM];     // fp32 (for scores1)
__device__ __half g_h1h[MAXN * H1DIM];    // fp16 mirror (for agg1 gather)
__device__ float  g_s1src[MAXN * HEADS1];
__device__ float  g_s1dst[MAXN * HEADS1];
__device__ int    g_deg[MAXN];
__device__ int    g_rowptr[MAXN + 1];
__device__ int    g_cursor[MAXN];
__device__ int    g_esrc[MAXE];
__device__ float  g_out1[MAXN * H1DIM];
__device__ float  g_h2[MAXN * H2DIM];     // fp32 (for scores2)
__device__ __half g_h2h[MAXN * H2DIM];    // fp16 mirror (for agg2 gather)
__device__ float  g_s2src[MAXN];
__device__ float  g_s2dst[MAXN];
__device__ int    g_is64;

// ---------------- helpers -----------------------------------------------------
__device__ __forceinline__ int edge_at(const void* ei, size_t idx) {
    if (g_is64) return (int)((const long long*)ei)[idx];
    return ((const int*)ei)[idx];
}

__device__ __forceinline__ float to_tf32(float x) {
    float r;
    asm("cvt.rna.tf32.f32 %0, %1;" : "=f"(r) : "f"(x));
    return r;
}

__device__ __forceinline__ float lrelu(float v) {
    return (v > 0.f) ? v : NEG_SLOPE * v;
}

__device__ __forceinline__ void mma_tf32(float* d, const unsigned* a,
                                         unsigned b0, unsigned b1) {
    asm volatile(
        "mma.sync.aligned.m16n8k8.row.col.f32.tf32.tf32.f32 "
        "{%0,%1,%2,%3}, {%4,%5,%6,%7}, {%8,%9}, {%0,%1,%2,%3};"
        : "+f"(d[0]), "+f"(d[1]), "+f"(d[2]), "+f"(d[3])
        : "r"(a[0]), "r"(a[1]), "r"(a[2]), "r"(a[3]), "r"(b0), "r"(b1));
}

// ---------------- init: deg=1 everywhere + edge-dtype detect ------------------
__global__ void init_kernel(const int* __restrict__ ei32, int Nn) {
    int i = blockIdx.x * blockDim.x + threadIdx.x;
    if (i < Nn) g_deg[i] = 1;   // self loop pre-counted
    if (i == 0) {
        int all_zero = 1;
        for (int k = 0; k < 64; k++)
            if (ei32[2 * k + 1] != 0) { all_zero = 0; break; }
        g_is64 = all_zero;
    }
}

// ---------------- tf32 tensor-core GEMM body (synchronous, KB=32) -------------
// Block tile 128 x BN; 256 threads. Writes fp32 C and fp16 mirror Ch.
// WHICH==0: A=arg(x), C=g_h1/g_h1h.  WHICH==1: A=g_out1, C=g_h2/g_h2h.
template <int BN, int WHICH>
__device__ __forceinline__ void gemm_body(const float* __restrict__ Aarg,
                                          const float* __restrict__ B,
                                          int M, int K, int bidx) {
    const float* __restrict__ A = (WHICH == 0) ? Aarg : (const float*)g_out1;
    float*  __restrict__ C  = (WHICH == 0) ? g_h1  : g_h2;
    __half* __restrict__ Ch = (WHICH == 0) ? g_h1h : g_h2h;

    constexpr int KB   = 32;
    constexpr int NW_N = BN / 64;
    constexpr int WM   = 128 / (8 / NW_N);
    constexpr int MAT  = WM / 16;
    constexpr int NAT  = 8;

    __shared__ float As[128][36];
    __shared__ float Bs[KB][BN + 4];

    const int tid  = threadIdx.x;
    const int wid  = tid >> 5;
    const int lane = tid & 31;
    const int wm   = (wid / NW_N) * WM;
    const int wn   = (wid % NW_N) * 64;
    const int bm   = bidx * 128;
    const int lq   = lane & 3;
    const int lg   = lane >> 2;

    float acc[MAT][NAT][4];
#pragma unroll
    for (int i = 0; i < MAT; i++)
#pragma unroll
        for (int j = 0; j < NAT; j++)
#pragma unroll
            for (int c = 0; c < 4; c++) acc[i][j][c] = 0.0f;

    for (int k0 = 0; k0 < K; k0 += KB) {
#pragma unroll
        for (int i = 0; i < 4; i++) {
            int idx = tid + i * 256;
            int row = idx >> 3;
            int kc  = (idx & 7) * 4;
            int gm  = bm + row;
            int gmc = (gm < M) ? gm : (M - 1);
            float4 v = *(const float4*)(A + (size_t)gmc * K + k0 + kc);
            if (gm >= M) v = make_float4(0.f, 0.f, 0.f, 0.f);
            v.x = to_tf32(v.x); v.y = to_tf32(v.y);
            v.z = to_tf32(v.z); v.w = to_tf32(v.w);
            *(float4*)&As[row][kc] = v;
        }
#pragma unroll
        for (int i = 0; i < (KB * BN) / (4 * 256); i++) {
            int idx = tid + i * 256;
            int kk  = idx / (BN / 4);
            int nc  = (idx % (BN / 4)) * 4;
            float4 v = *(const float4*)(B + (size_t)(k0 + kk) * BN + nc);
            v.x = to_tf32(v.x); v.y = to_tf32(v.y);
            v.z = to_tf32(v.z); v.w = to_tf32(v.w);
            *(float4*)&Bs[kk][nc] = v;
        }
        __syncthreads();
#pragma unroll
        for (int ks = 0; ks < KB; ks += 8) {
            unsigned a[MAT][4];
#pragma unroll
            for (int i = 0; i < MAT; i++) {
                int m0 = wm + i * 16;
                a[i][0] = __float_as_uint(As[m0 + lg][ks + lq]);
                a[i][1] = __float_as_uint(As[m0 + lg + 8][ks + lq]);
                a[i][2] = __float_as_uint(As[m0 + lg][ks + lq + 4]);
                a[i][3] = __float_as_uint(As[m0 + lg + 8][ks + lq + 4]);
            }
#pragma unroll
            for (int j = 0; j < NAT; j++) {
                unsigned b0 = __float_as_uint(Bs[ks + lq][wn + j * 8 + lg]);
                unsigned b1 = __float_as_uint(Bs[ks + lq + 4][wn + j * 8 + lg]);
#pragma unroll
                for (int i = 0; i < MAT; i++) mma_tf32(acc[i][j], a[i], b0, b1);
            }
        }
        __syncthreads();
    }
#pragma unroll
    for (int i = 0; i < MAT; i++) {
#pragma unroll
        for (int j = 0; j < NAT; j++) {
            int gm = bm + wm + i * 16 + lg;
            int n0 = wn + j * 8 + 2 * lq;
            if (gm < M) {
                *(float2*)(C + (size_t)gm * BN + n0) =
                    make_float2(acc[i][j][0], acc[i][j][1]);
                *(__half2*)(Ch + (size_t)gm * BN + n0) =
                    __floats2half2_rn(acc[i][j][0], acc[i][j][1]);
            }
            if (gm + 8 < M) {
                *(float2*)(C + (size_t)(gm + 8) * BN + n0) =
                    make_float2(acc[i][j][2], acc[i][j][3]);
                *(__half2*)(Ch + (size_t)(gm + 8) * BN + n0) =
                    __floats2half2_rn(acc[i][j][2], acc[i][j][3]);
            }
        }
    }
}

// ---------------- K1: gemm1 blocks || histo blocks ----------------------------
__global__ __launch_bounds__(256)
void k1_gemm1_histo(const float* __restrict__ x, const float* __restrict__ W1,
                    const void* __restrict__ ei, int M, int E, int nGemmBlocks) {
    if ((int)blockIdx.x < nGemmBlocks) {
        gemm_body<H1DIM, 0>(x, W1, M, IN_DIM, blockIdx.x);
    } else {
        int e = (blockIdx.x - nGemmBlocks) * 256 + threadIdx.x;
        if (e < E) atomicAdd(&g_deg[edge_at(ei, (size_t)E + e)], 1);
    }
}

// ---------------- single-kernel coalesced scan (shfl-based) -------------------
__global__ __launch_bounds__(SCAN_B)
void scan_kernel(int Nn) {
    __shared__ int wsum[32];
    __shared__ int wpre[32];
    __shared__ int boff;
    int tid = threadIdx.x, b = blockIdx.x;
    int lane = tid & 31, w = tid >> 5;

    // (a) block offset: reduce deg[0 .. b*1024) with coalesced loads
    int tot = 0;
    for (int i = tid; i < b * SCAN_B; i += SCAN_B) tot += g_deg[i];
#pragma unroll
    for (int o = 16; o > 0; o >>= 1) tot += __shfl_xor_sync(0xFFFFFFFFu, tot, o);
    if (lane == 0) wsum[w] = tot;
    __syncthreads();
    if (w == 0) {
        int s = wsum[lane];
#pragma unroll
        for (int o = 16; o > 0; o >>= 1) s += __shfl_xor_sync(0xFFFFFFFFu, s, o);
        if (lane == 0) boff = s;
    }

    // (b) per-block shfl scan
    int i = b * SCAN_B + tid;
    int v = (i < Nn) ? g_deg[i] : 0;
    int incl = v;
#pragma unroll
    for (int o = 1; o < 32; o <<= 1) {
        int u = __shfl_up_sync(0xFFFFFFFFu, incl, o);
        if (lane >= o) incl += u;
    }
    if (lane == 31) wsum[w] = incl;
    __syncthreads();
    if (w == 0) {
        int t = wsum[lane];
        int inc = t;
#pragma unroll
        for (int o = 1; o < 32; o <<= 1) {
            int u = __shfl_up_sync(0xFFFFFFFFu, inc, o);
            if (lane >= o) inc += u;
        }
        wpre[lane] = inc - t;
    }
    __syncthreads();

    int excl = boff + wpre[w] + incl - v;
    if (i < Nn) {
        g_rowptr[i] = excl;
        g_cursor[i] = excl;
    }
    if (i == Nn - 1) g_rowptr[Nn] = excl + v;
}

// ---------------- K2: scores1 blocks || scatter blocks -------------------------
__global__ __launch_bounds__(256)
void k2_scores1_scatter(const float* __restrict__ a1s, const float* __restrict__ a1d,
                        const void* __restrict__ ei, int Nn, int E, int nScoreBlocks) {
    if ((int)blockIdx.x < nScoreBlocks) {
        int idx = blockIdx.x * 256 + threadIdx.x;
        if (idx >= Nn * HEADS1) return;
        int n = idx >> 3, h = idx & 7;
        const float4* hp = (const float4*)(g_h1 + (size_t)n * H1DIM + h * 16);
        const float4* as = (const float4*)(a1s + h * 16);
        const float4* ad = (const float4*)(a1d + h * 16);
        float ss = 0.f, sd = 0.f;
#pragma unroll
        for (int q = 0; q < 4; q++) {
            float4 v = hp[q], s4 = as[q], d4 = ad[q];
            ss += v.x * s4.x + v.y * s4.y + v.z * s4.z + v.w * s4.w;
            sd += v.x * d4.x + v.y * d4.y + v.z * d4.z + v.w * d4.w;
        }
        g_s1src[idx] = ss;
        g_s1dst[idx] = sd;
    } else {
        int idx = (blockIdx.x - nScoreBlocks) * 256 + threadIdx.x;
        if (idx >= E + Nn) return;
        int src, dst;
        if (idx < E) {
            src = edge_at(ei, (size_t)idx);
            dst = edge_at(ei, (size_t)E + idx);
        } else {
            src = dst = idx - E;  // self loop
        }
        int pos = atomicAdd(&g_cursor[dst], 1);
        g_esrc[pos] = src;
    }
}

// ---------------- layer-1 softmax+agg (fp16 gather, coalesced esrc) -----------
__global__ __launch_bounds__(256)
void agg1_kernel(const float* __restrict__ b1, int Nn) {
    int warp = (blockIdx.x * blockDim.x + threadIdx.x) >> 5;
    int lane = threadIdx.x & 31;
    if (warp >= Nn) return;
    int beg = g_rowptr[warp], end = g_rowptr[warp + 1];
    const int head = lane >> 2;
    const float sdst = g_s1dst[(size_t)warp * HEADS1 + head];

    float4 acc = make_float4(0.f, 0.f, 0.f, 0.f);
    float s = 0.f;
    int j = beg;
    for (; j + 7 < end; j += 8) {
        int eidx = g_esrc[j + (lane & 7)];
        int   idx[8];
        float w[8];
        uint2 u[8];
#pragma unroll
        for (int t = 0; t < 8; t++) idx[t] = __shfl_sync(0xFFFFFFFFu, eidx, t);
#pragma unroll
        for (int t = 0; t < 8; t++)
            u[t] = *(const uint2*)(g_h1h + (size_t)idx[t] * H1DIM + lane * 4);
#pragma unroll
        for (int t = 0; t < 8; t++)
            w[t] = __expf(lrelu(g_s1src[(size_t)idx[t] * HEADS1 + head] + sdst));
#pragma unroll
        for (int t = 0; t < 8; t++) {
            s += w[t];
            float2 p = __half22float2(*(__half2*)&u[t].x);
            float2 q = __half22float2(*(__half2*)&u[t].y);
            acc.x = fmaf(w[t], p.x, acc.x); acc.y = fmaf(w[t], p.y, acc.y);
            acc.z = fmaf(w[t], q.x, acc.z); acc.w = fmaf(w[t], q.y, acc.w);
        }
    }
    for (; j < end; ++j) {
        int i0 = g_esrc[j];
        float w0 = __expf(lrelu(g_s1src[(size_t)i0 * HEADS1 + head] + sdst));
        uint2 u0 = *(const uint2*)(g_h1h + (size_t)i0 * H1DIM + lane * 4);
        s += w0;
        float2 p = __half22float2(*(__half2*)&u0.x);
        float2 q = __half22float2(*(__half2*)&u0.y);
        acc.x = fmaf(w0, p.x, acc.x); acc.y = fmaf(w0, p.y, acc.y);
        acc.z = fmaf(w0, q.x, acc.z); acc.w = fmaf(w0, q.y, acc.w);
    }
    float inv = 1.0f / s;
    float4 bb = *(const float4*)(b1 + lane * 4);
    float4 o;
    o.x = acc.x * inv + bb.x;  o.y = acc.y * inv + bb.y;
    o.z = acc.z * inv + bb.z;  o.w = acc.w * inv + bb.w;
    o.x = (o.x > 0.f) ? o.x : (__expf(o.x) - 1.0f);
    o.y = (o.y > 0.f) ? o.y : (__expf(o.y) - 1.0f);
    o.z = (o.z > 0.f) ? o.z : (__expf(o.z) - 1.0f);
    o.w = (o.w > 0.f) ? o.w : (__expf(o.w) - 1.0f);
    *(float4*)(g_out1 + (size_t)warp * H1DIM + lane * 4) = o;
}

// ---------------- gemm2 (standalone) ------------------------------------------
__global__ __launch_bounds__(256)
void gemm2_kernel(const float* __restrict__ W2, int M) {
    gemm_body<H2DIM, 1>(nullptr, W2, M, H1DIM, blockIdx.x);
}

// ---------------- layer-2 scores (warp per node) -------------------------------
__global__ __launch_bounds__(256)
void scores2_kernel(const float* __restrict__ a2s, const float* __restrict__ a2d, int Nn) {
    int warp = (blockIdx.x * blockDim.x + threadIdx.x) >> 5;
    int lane = threadIdx.x & 31;
    if (warp >= Nn) return;
    const float2 v  = *(const float2*)(g_h2 + (size_t)warp * H2DIM + lane * 2);
    const float2 s2 = *(const float2*)(a2s + lane * 2);
    const float2 d2 = *(const float2*)(a2d + lane * 2);
    float ss = v.x * s2.x + v.y * s2.y;
    float sd = v.x * d2.x + v.y * d2.y;
#pragma unroll
    for (int o = 16; o > 0; o >>= 1) {
        ss += __shfl_xor_sync(0xFFFFFFFFu, ss, o);
        sd += __shfl_xor_sync(0xFFFFFFFFu, sd, o);
    }
    if (lane == 0) {
        g_s2src[warp] = ss;
        g_s2dst[warp] = sd;
    }
}

// ---------------- layer-2 softmax+agg (fp16 gather, coalesced esrc) -----------
__global__ __launch_bounds__(256)
void agg2_kernel(const float* __restrict__ b2, float* __restrict__ dout, int Nn) {
    int warp = (blockIdx.x * blockDim.x + threadIdx.x) >> 5;
    int lane = threadIdx.x & 31;
    if (warp >= Nn) return;
    int beg = g_rowptr[warp], end = g_rowptr[warp + 1];
    const float sdst = g_s2dst[warp];

    float a0 = 0.f, a1 = 0.f, s = 0.f;
    int j = beg;
    for (; j + 7 < end; j += 8) {
        int eidx = g_esrc[j + (lane & 7)];
        int     idx[8];
        float   w[8];
        __half2 u[8];
#pragma unroll
        for (int t = 0; t < 8; t++) idx[t] = __shfl_sync(0xFFFFFFFFu, eidx, t);
#pragma unroll
        for (int t = 0; t < 8; t++)
            u[t] = *(const __half2*)(g_h2h + (size_t)idx[t] * H2DIM + lane * 2);
#pragma unroll
        for (int t = 0; t < 8; t++)
            w[t] = __expf(lrelu(g_s2src[idx[t]] + sdst));
#pragma unroll
        for (int t = 0; t < 8; t++) {
            s += w[t];
            float2 f = __half22float2(u[t]);
            a0 = fmaf(w[t], f.x, a0); a1 = fmaf(w[t], f.y, a1);
        }
    }
    for (; j < end; ++j) {
        int i0 = g_esrc[j];
        float w0 = __expf(lrelu(g_s2src[i0] + sdst));
        __half2 u0 = *(const __half2*)(g_h2h + (size_t)i0 * H2DIM + lane * 2);
        s += w0;
        float2 f = __half22float2(u0);
        a0 = fmaf(w0, f.x, a0); a1 = fmaf(w0, f.y, a1);
    }
    float inv = 1.0f / s;
    float2 bb = *(const float2*)(b2 + lane * 2);
    float o0 = a0 * inv + bb.x;
    float o1 = a1 * inv + bb.y;

    float mx = fmaxf(o0, o1);
#pragma unroll
    for (int o = 16; o > 0; o >>= 1) mx = fmaxf(mx, __shfl_xor_sync(0xFFFFFFFFu, mx, o));
    float se = __expf(o0 - mx) + __expf(o1 - mx);
#pragma unroll
    for (int o = 16; o > 0; o >>= 1) se += __shfl_xor_sync(0xFFFFFFFFu, se, o);
    float lse = __logf(se);
    float2 r;  r.x = o0 - mx - lse;  r.y = o1 - mx - lse;
    *(float2*)(dout + (size_t)warp * H2DIM + lane * 2) = r;
}

// ---------------- launch (pure kernel launches, default stream) --------------
extern "C" void kernel_launch(void* const* d_in, const int* in_sizes, int n_in,
                              void* d_out, int out_size) {
    const float* x   = (const float*)d_in[0];
    const void*  ei  = d_in[1];
    const float* W1  = (const float*)d_in[2];
    const float* a1s = (const float*)d_in[3];
    const float* a1d = (const float*)d_in[4];
    const float* b1  = (const float*)d_in[5];
    const float* W2  = (const float*)d_in[6];
    const float* a2s = (const float*)d_in[7];
    const float* a2d = (const float*)d_in[8];
    const float* b2  = (const float*)d_in[9];
    float*       out = (float*)d_out;

    const int Nn   = in_sizes[0] / IN_DIM;  // 50000
    const int E    = in_sizes[1] / 2;       // 800000
    const int Etot = E + Nn;

    const int nG1 = (Nn + 127) / 128;             // gemm1 blocks
    const int nH  = (E + 255) / 256;              // histo blocks
    const int nS1 = (Nn * HEADS1 + 255) / 256;    // scores1 blocks
    const int nSc = (Etot + 255) / 256;           // scatter blocks
    const int nSB = (Nn + SCAN_B - 1) / SCAN_B;   // scan blocks (49)

    init_kernel<<<(Nn + 255) / 256, 256>>>((const int*)ei, Nn);
    k1_gemm1_histo<<<nG1 + nH, 256>>>(x, W1, ei, Nn, E, nG1);
    scan_kernel<<<nSB, SCAN_B>>>(Nn);
    k2_scores1_scatter<<<nS1 + nSc, 256>>>(a1s, a1d, ei, Nn, E, nS1);
    agg1_kernel<<<(Nn + 7) / 8, 256>>>(b1, Nn);

    gemm2_kernel<<<(Nn + 127) / 128, 256>>>(W2, Nn);
    scores2_kernel<<<(Nn + 7) / 8, 256>>>(a2s, a2d, Nn);
    agg2_kernel<<<(Nn + 7) / 8, 256>>>(b2, out, Nn);
}